// round 16
// baseline (speedup 1.0000x reference)
#include <cuda_runtime.h>
#include <cuda_bf16.h>
#include <cstdint>

#define BB 2
#define SS 2048
#define DD 1024
#define NHQ 16
#define NKVH 4
#define HDH 64
#define EE 8
#define HIDM 1365
#define HIDP 1376
#define CAPE 1280
#define TT 4096

typedef __nv_bfloat16 bf16;

__device__ __align__(128) float g_q  [TT*DD];
__device__ __align__(128) float g_k  [TT*NKVH*HDH];
__device__ __align__(128) float g_h  [TT*DD];
__device__ __align__(128) float g_hn [TT*DD];
__device__ float g_probs[TT*EE];
__device__ int   g_ridx[TT*2];
__device__ float g_rwt [TT*2];
__device__ int   g_ecnt[EE];
__device__ int   g_eidx[EE*CAPE];
__device__ float g_ew  [EE*CAPE];

__device__ __align__(128) bf16 g_xnb [2*TT*DD];
__device__ __align__(128) bf16 g_aob [2*TT*DD];
__device__ __align__(128) bf16 g_hnb [2*TT*DD];
__device__ __align__(128) bf16 g_h1sb[2*TT*HIDP];
__device__ __align__(128) bf16 g_eh1b[2*EE*CAPE*HIDP];
__device__ __align__(128) bf16 g_qb  [2*TT*DD];
__device__ __align__(128) bf16 g_kb  [2*TT*256];
__device__ __align__(128) bf16 g_vb  [2*TT*256];
__device__ __align__(128) bf16 g_wqb [2*DD*DD];
__device__ __align__(128) bf16 g_wkb [2*DD*256];
__device__ __align__(128) bf16 g_wvb [2*DD*256];
__device__ __align__(128) bf16 g_wob [2*DD*DD];
__device__ __align__(128) bf16 g_sw1b[2*DD*HIDP];
__device__ __align__(128) bf16 g_sw3b[2*DD*HIDP];
__device__ __align__(128) bf16 g_sw2b[2*HIDP*DD];
__device__ __align__(128) bf16 g_ew1b[2*EE*DD*HIDP];
__device__ __align__(128) bf16 g_ew3b[2*EE*DD*HIDP];
__device__ __align__(128) bf16 g_ew2b[2*EE*HIDP*DD];

__device__ __forceinline__ void cpa16(uint32_t s, const void* g){
    asm volatile("cp.async.cg.shared.global [%0], [%1], 16;"::"r"(s),"l"(g));
}
__device__ __forceinline__ void cp_commit(){ asm volatile("cp.async.commit_group;"); }
template<int N> __device__ __forceinline__ void cp_wait(){ asm volatile("cp.async.wait_group %0;"::"n"(N)); }
__device__ __forceinline__ void ldsm4(uint32_t (&r)[4], uint32_t a){
    asm volatile("ldmatrix.sync.aligned.m8n8.x4.shared.b16 {%0,%1,%2,%3}, [%4];"
        :"=r"(r[0]),"=r"(r[1]),"=r"(r[2]),"=r"(r[3]):"r"(a));
}
__device__ __forceinline__ void ldsm4t(uint32_t (&r)[4], uint32_t a){
    asm volatile("ldmatrix.sync.aligned.m8n8.x4.trans.shared.b16 {%0,%1,%2,%3}, [%4];"
        :"=r"(r[0]),"=r"(r[1]),"=r"(r[2]),"=r"(r[3]):"r"(a));
}
__device__ __forceinline__ void mma16816(float (&d)[4], const uint32_t (&a)[4], uint32_t b0, uint32_t b1){
    asm volatile("mma.sync.aligned.m16n8k16.row.col.f32.bf16.bf16.f32 "
        "{%0,%1,%2,%3}, {%4,%5,%6,%7}, {%8,%9}, {%0,%1,%2,%3};"
        :"+f"(d[0]),"+f"(d[1]),"+f"(d[2]),"+f"(d[3])
        :"r"(a[0]),"r"(a[1]),"r"(a[2]),"r"(a[3]),"r"(b0),"r"(b1));
}
__device__ __forceinline__ void split2(float x, float y, uint32_t& hi, uint32_t& lo){
    __nv_bfloat162 h = __floats2bfloat162_rn(x, y);
    __nv_bfloat162 l = __floats2bfloat162_rn(x - __bfloat162float(h.x), y - __bfloat162float(h.y));
    hi = *(uint32_t*)&h; lo = *(uint32_t*)&l;
}

// ---- split convert fp32 -> hi/lo bf16 (4-wide vectorized) ----
struct CDesc { const float* in; bf16* hi; bf16* lo; int Rin, Cin, Rp, Cp; };
struct CBatch { CDesc d[16]; };
__global__ __launch_bounds__(256) void convert_kernel(CBatch cb){
    CDesc c = cb.d[blockIdx.z];
    long tot4 = ((long)c.Rp * c.Cp) >> 2;
    for (long q = (long)blockIdx.x*blockDim.x + threadIdx.x; q < tot4; q += (long)gridDim.x*blockDim.x){
        long i = q << 2;
        int r = (int)(i / c.Cp), cc = (int)(i % c.Cp);
        uint32_t hv[2], lv[2];
        const float* src = c.in + (long)r*c.Cin + cc;
        bool rin = r < c.Rin;
        #pragma unroll
        for (int p = 0; p < 2; p++){
            float v0 = (rin && cc+2*p   < c.Cin) ? src[2*p]   : 0.f;
            float v1 = (rin && cc+2*p+1 < c.Cin) ? src[2*p+1] : 0.f;
            split2(v0, v1, hv[p], lv[p]);
        }
        *(uint2*)&c.hi[i] = make_uint2(hv[0], hv[1]);
        *(uint2*)&c.lo[i] = make_uint2(lv[0], lv[1]);
    }
}

// ---- batched split-bf16 HMMA GEMM, 128x64 CTA tile (DUAL: fused w1||w3 + silu) ----
struct GDesc {
    const bf16 *Ah, *Al, *Bh, *Bl, *B2h, *B2l;
    float* C; const float* res;
    const int* aidx; const int* cidx; const float* rs; const int* Mcnt;
    bf16 *Chi, *Clo;
    int M, N, K, ldb, ldc;
};
struct GBatch { GDesc d[18]; };

#define ASTR 40
#define BSTR 72
#define ASZH (128*ASTR)
#define BSZH (32*BSTR)

template<int DUAL>
__global__ __launch_bounds__(256, DUAL ? 2 : 3) void bgemm_kernel(GBatch gb){
    GDesc g = gb.d[blockIdx.z];
    const int Meff = g.Mcnt ? *g.Mcnt : g.M;
    const int row0 = blockIdx.y*128, col0 = blockIdx.x*64;
    if (row0 >= Meff || col0 >= g.N) return;
    const int BUFH_ = 2*ASZH + (DUAL?4:2)*BSZH;

    extern __shared__ bf16 sh[];
    const int tid = threadIdx.x;
    const int ra = tid>>2, ca = (tid&3)*8;
    const int rbn = tid>>3, cbn = (tid&7)*8;
    int ar0, ar1;
    { int r0g = row0+ra, r1g = row0+ra+64;
      if (g.aidx){ ar0 = g.aidx[min(r0g,Meff-1)]; ar1 = g.aidx[min(r1g,Meff-1)]; }
      else { ar0 = r0g < g.M ? r0g : g.M-1; ar1 = r1g < g.M ? r1g : g.M-1; } }
    const char* pAh0 = (const char*)(g.Ah + (long)ar0*g.K + ca);
    const char* pAl0 = (const char*)(g.Al + (long)ar0*g.K + ca);
    const char* pAh1 = (const char*)(g.Ah + (long)ar1*g.K + ca);
    const char* pAl1 = (const char*)(g.Al + (long)ar1*g.K + ca);
    const bool bval = (col0+cbn) < g.ldb;
    const long boff = (long)rbn*g.ldb + col0+cbn;
    const long bstride = 64L*g.ldb;

    const uint32_t smb = (uint32_t)__cvta_generic_to_shared(sh);
    const uint32_t aH0 = 2*(ra*ASTR+ca), aH1 = aH0 + 2*64*ASTR;
    const uint32_t aL0 = aH0 + 2*ASZH, aL1 = aH1 + 2*ASZH;
    const uint32_t bO = 2*(2*ASZH + rbn*BSTR + cbn);

    if (!bval){
        uint4 z = make_uint4(0,0,0,0);
        #pragma unroll
        for (int buf = 0; buf < 2; buf++)
            for (int p = 0; p < (DUAL?4:2); p++)
                *(uint4*)(sh + buf*BUFH_ + 2*ASZH + p*BSZH + rbn*BSTR + cbn) = z;
    }
    const int NT = g.K >> 5;
    auto issue = [&](int t, int buf){
        uint32_t o = smb + (uint32_t)buf*(BUFH_*2);
        long ta = (long)t*64;
        cpa16(o+aH0, pAh0+ta); cpa16(o+aH1, pAh1+ta);
        cpa16(o+aL0, pAl0+ta); cpa16(o+aL1, pAl1+ta);
        if (bval){
            long tb = (long)t*bstride;
            cpa16(o+bO,          (const char*)(g.Bh+boff)+tb);
            cpa16(o+bO+2*BSZH,   (const char*)(g.Bl+boff)+tb);
            if (DUAL){
                cpa16(o+bO+4*BSZH, (const char*)(g.B2h+boff)+tb);
                cpa16(o+bO+6*BSZH, (const char*)(g.B2l+boff)+tb);
            }
        }
    };
    issue(0,0); cp_commit();

    const int warp = tid>>5, lane = tid&31;
    const int wm = (warp&3)*32, wn = (warp>>2)*32;
    float acc[2][4][4] = {};
    float acc2[DUAL?2:1][4][4] = {};
    const uint32_t aLd = (uint32_t)((wm + (lane&15))*ASTR + (lane>>4)*8);
    const uint32_t bLd = (uint32_t)(((lane&7) + ((lane>>3)&1)*8)*BSTR + wn + (lane>>4)*8);

    for (int t = 0; t < NT; t++){
        if (t+1 < NT){ issue(t+1, (t+1)&1); cp_commit(); cp_wait<1>(); }
        else cp_wait<0>();
        __syncthreads();
        const uint32_t base = smb + (uint32_t)(t&1)*(BUFH_*2);
        #pragma unroll
        for (int ks = 0; ks < 2; ks++){
            uint32_t bh[2][4], bl[2][4], b2h[2][4], b2l[2][4];
            #pragma unroll
            for (int np = 0; np < 2; np++){
                uint32_t ad = base + 2*(2*ASZH + bLd + ks*16*BSTR + np*16);
                ldsm4t(bh[np], ad); ldsm4t(bl[np], ad + 2*BSZH);
                if (DUAL){ ldsm4t(b2h[np], ad + 4*BSZH); ldsm4t(b2l[np], ad + 6*BSZH); }
            }
            #pragma unroll
            for (int mt = 0; mt < 2; mt++){
                uint32_t aa = base + 2*(aLd + mt*16*ASTR + ks*16);
                uint32_t ah[4], al[4];
                ldsm4(ah, aa); ldsm4(al, aa + 2*ASZH);
                #pragma unroll
                for (int nt = 0; nt < 4; nt++){
                    int np = nt>>1, o = (nt&1)*2;
                    mma16816(acc[mt][nt], ah, bh[np][o], bh[np][o+1]);
                    mma16816(acc[mt][nt], al, bh[np][o], bh[np][o+1]);
                    mma16816(acc[mt][nt], ah, bl[np][o], bl[np][o+1]);
                    if (DUAL){
                        mma16816(acc2[mt][nt], ah, b2h[np][o], b2h[np][o+1]);
                        mma16816(acc2[mt][nt], al, b2h[np][o], b2h[np][o+1]);
                        mma16816(acc2[mt][nt], ah, b2l[np][o], b2l[np][o+1]);
                    }
                }
            }
        }
        __syncthreads();
    }

    const int Nt = g.N, ldc = g.ldc;
    #pragma unroll
    for (int mt = 0; mt < 2; mt++)
    #pragma unroll
    for (int dh = 0; dh < 2; dh++){
        int r = row0 + wm + mt*16 + (lane>>2) + dh*8;
        if (r >= Meff) continue;
        #pragma unroll
        for (int nt = 0; nt < 4; nt++){
            int c = col0 + wn + nt*8 + (lane&3)*2;
            float v0 = acc[mt][nt][dh*2], v1 = acc[mt][nt][dh*2+1];
            if (DUAL){
                if (c+1 < Nt){
                    float w0 = acc2[mt][nt][dh*2], w1 = acc2[mt][nt][dh*2+1];
                    float s0 = (v0/(1.f+__expf(-v0)))*w0;
                    float s1 = (v1/(1.f+__expf(-v1)))*w1;
                    long ro = (long)r*ldc + c;
                    uint32_t hi, lo; split2(s0, s1, hi, lo);
                    *(uint32_t*)&g.Chi[ro] = hi;
                    *(uint32_t*)&g.Clo[ro] = lo;
                }
            } else if (g.cidx){
                float w = g.rs[r]; long ro = (long)g.cidx[r]*ldc;
                if (c < Nt)   atomicAdd(&g.C[ro+c], w*v0);
                if (c+1 < Nt) atomicAdd(&g.C[ro+c+1], w*v1);
            } else {
                long ro = (long)r*ldc;
                if (g.res){ if (c < Nt) v0 += g.res[ro+c]; if (c+1 < Nt) v1 += g.res[ro+c+1]; }
                if (g.C){
                    if (c < Nt)   g.C[ro+c]   = v0;
                    if (c+1 < Nt) g.C[ro+c+1] = v1;
                }
                if (g.Chi && c+1 < Nt){
                    uint32_t hi, lo; split2(v0, v1, hi, lo);
                    *(uint32_t*)&g.Chi[ro+c] = hi;
                    *(uint32_t*)&g.Clo[ro+c] = lo;
                }
            }
        }
    }
}

// ---- rmsnorm ----
__global__ __launch_bounds__(256) void rmsnorm_kernel(
    const float* __restrict__ x, const float* __restrict__ w,
    float* __restrict__ yf, bf16* __restrict__ yh, bf16* __restrict__ yl){
    long t = blockIdx.x;
    const float* xr = x + t*DD;
    float ss = 0.f;
    for (int d = threadIdx.x; d < DD; d += 256){ float v = xr[d]; ss += v*v; }
    for (int off = 16; off; off >>= 1) ss += __shfl_xor_sync(0xffffffffu, ss, off);
    __shared__ float red[8]; __shared__ float rfac;
    if ((threadIdx.x&31) == 0) red[threadIdx.x>>5] = ss;
    __syncthreads();
    if (threadIdx.x == 0){
        float s2 = 0.f;
        #pragma unroll
        for (int i = 0; i < 8; i++) s2 += red[i];
        rfac = rsqrtf(s2/(float)DD + 1e-6f);
    }
    __syncthreads();
    float r = rfac;
    for (int d = threadIdx.x; d < DD; d += 256){
        float v = xr[d]*r*w[d];
        if (yf) yf[t*DD + d] = v;
        bf16 h = __float2bfloat16(v);
        yh[t*DD + d] = h;
        yl[t*DD + d] = __float2bfloat16(v - __bfloat162float(h));
    }
}

// ---- combined RoPE ----
__global__ void rope2_kernel(const float* __restrict__ qin, const float* __restrict__ kin,
    float* __restrict__ nk, bf16* __restrict__ qh, bf16* __restrict__ ql,
    bf16* __restrict__ kh, bf16* __restrict__ kl,
    const float* __restrict__ cs, const float* __restrict__ sn){
    const int qtot = TT*NHQ*32, ktot = TT*NKVH*32;
    for (int idx = blockIdx.x*blockDim.x + threadIdx.x; idx < qtot + ktot; idx += gridDim.x*blockDim.x){
        const float* in; bf16 *oh, *ol; float* of; int H, i;
        if (idx < qtot){ in = qin; oh = qh; ol = ql; of = nullptr; H = NHQ; i = idx; }
        else { in = kin; oh = kh; ol = kl; of = nk; H = NKVH; i = idx - qtot; }
        int d = i & 31, h = (i>>5)%H, t = i/(32*H), s = t & (SS-1);
        long base = ((long)t*H + h)*HDH + d;
        float x1 = in[base], x2 = in[base+32];
        float c = cs[s*HDH+d], si = sn[s*HDH+d];
        float y1 = x1*c - x2*si, y2 = x1*si + x2*c;
        if (of){ of[base] = y1; of[base+32] = y2; }
        bf16 h1 = __float2bfloat16(y1), h2 = __float2bfloat16(y2);
        oh[base] = h1; oh[base+32] = h2;
        ol[base]    = __float2bfloat16(y1 - __bfloat162float(h1));
        ol[base+32] = __float2bfloat16(y2 - __bfloat162float(h2));
    }
}

// ---- flash attention: 2 heads/CTA share K/V, double-buffered ----
#define FSTR 72
#define FPL (64*FSTR)
#define FSMEM (12*FPL*2)

__global__ __launch_bounds__(256, 2) void flash_tc_kernel(
    const bf16* __restrict__ Qb, const bf16* __restrict__ Kb,
    const bf16* __restrict__ Vb, bf16* __restrict__ Oh, bf16* __restrict__ Ol){
    const int b = blockIdx.z, hp2 = blockIdx.y, qt = blockIdx.x;
    const int hk = hp2 >> 1, s0 = qt*64;
    extern __shared__ bf16 fs[];
    const uint32_t smb = (uint32_t)__cvta_generic_to_shared(fs);
    const int tid = threadIdx.x, wid = tid>>5, lane = tid&31;
    const int wg = wid>>2, w4 = wid&3;
    const int h = hp2*2 + wg;
    const long QPL = (long)TT*NHQ*HDH, KPL = (long)TT*NKVH*HDH;
    const int wrow = w4*16;

    for (int i = tid; i < 2048; i += 256){
        int pl = i>>9, r = (i>>3)&63, c8 = (i&7)*8;
        const bf16* src = Qb + (long)(pl&1)*QPL + ((long)((b*SS+s0+r)*NHQ) + hp2*2 + (pl>>1))*HDH + c8;
        cpa16(smb + 2*(pl*FPL + r*FSTR + c8), src);
    }
    auto loadKV = [&](int kt, int buf){
        for (int i = tid; i < 2048; i += 256){
            int pl = i>>9, r = (i>>3)&63, c8 = (i&7)*8;
            const bf16* basep = (pl < 2) ? Kb : Vb;
            const bf16* src = basep + (long)(pl&1)*KPL + ((long)((b*SS+kt*64+r)*NKVH) + hk)*HDH + c8;
            cpa16(smb + 2*((4 + buf*4 + pl)*FPL + r*FSTR + c8), src);
        }
        cp_commit();
    };
    loadKV(0, 0);

    float acc_o[8][4] = {};
    float m0 = -1e30f, m1 = -1e30f, l0 = 0.f, l1 = 0.f;
    const int colb = (lane&3)*2;
    const int rl0 = wrow + (lane>>2), rl1 = rl0 + 8;
    const uint32_t aQh = smb + 2*((2*wg)*FPL + (wrow + (lane&15))*FSTR + (lane>>4)*8);
    const uint32_t aQl = aQh + 2*FPL;

    for (int kt = 0; kt <= qt; kt++){
        if (kt+1 <= qt){ loadKV(kt+1, (kt+1)&1); cp_wait<1>(); }
        else cp_wait<0>();
        __syncthreads();
        const uint32_t kb0 = smb + 2*(uint32_t)((4 + (kt&1)*4)*FPL);

        float s[8][4] = {};
        #pragma unroll
        for (int kst = 0; kst < 4; kst++){
            uint32_t ah[4], al[4];
            ldsm4(ah, aQh + 2*(kst*16));
            ldsm4(al, aQl + 2*(kst*16));
            #pragma unroll
            for (int ng = 0; ng < 4; ng++){
                uint32_t kh[4], kl[4];
                uint32_t ka = kb0 + 2*((ng*16 + (lane&15))*FSTR + kst*16 + (lane>>4)*8);
                ldsm4(kh, ka); ldsm4(kl, ka + 2*FPL);
                mma16816(s[2*ng],   ah, kh[0], kh[2]);
                mma16816(s[2*ng],   al, kh[0], kh[2]);
                mma16816(s[2*ng],   ah, kl[0], kl[2]);
                mma16816(s[2*ng+1], ah, kh[1], kh[3]);
                mma16816(s[2*ng+1], al, kh[1], kh[3]);
                mma16816(s[2*ng+1], ah, kl[1], kl[3]);
            }
        }
        const bool diag = (kt == qt);
        #pragma unroll
        for (int nt = 0; nt < 8; nt++){
            int c = nt*8 + colb;
            #pragma unroll
            for (int j = 0; j < 4; j++) s[nt][j] *= 0.125f;
            if (diag){
                if (c   > rl0) s[nt][0] = -1e30f;
                if (c+1 > rl0) s[nt][1] = -1e30f;
                if (c   > rl1) s[nt][2] = -1e30f;
                if (c+1 > rl1) s[nt][3] = -1e30f;
            }
        }
        float rm0 = -1e30f, rm1 = -1e30f;
        #pragma unroll
        for (int nt = 0; nt < 8; nt++){
            rm0 = fmaxf(rm0, fmaxf(s[nt][0], s[nt][1]));
            rm1 = fmaxf(rm1, fmaxf(s[nt][2], s[nt][3]));
        }
        rm0 = fmaxf(rm0, __shfl_xor_sync(0xffffffffu, rm0, 1));
        rm0 = fmaxf(rm0, __shfl_xor_sync(0xffffffffu, rm0, 2));
        rm1 = fmaxf(rm1, __shfl_xor_sync(0xffffffffu, rm1, 1));
        rm1 = fmaxf(rm1, __shfl_xor_sync(0xffffffffu, rm1, 2));
        float mn0 = fmaxf(m0, rm0), mn1 = fmaxf(m1, rm1);
        float al0 = __expf(m0 - mn0), al1 = __expf(m1 - mn1);
        m0 = mn0; m1 = mn1;
        float sum0 = 0.f, sum1 = 0.f;
        #pragma unroll
        for (int nt = 0; nt < 8; nt++){
            s[nt][0] = __expf(s[nt][0] - mn0); s[nt][1] = __expf(s[nt][1] - mn0);
            s[nt][2] = __expf(s[nt][2] - mn1); s[nt][3] = __expf(s[nt][3] - mn1);
            sum0 += s[nt][0] + s[nt][1]; sum1 += s[nt][2] + s[nt][3];
        }
        sum0 += __shfl_xor_sync(0xffffffffu, sum0, 1); sum0 += __shfl_xor_sync(0xffffffffu, sum0, 2);
        sum1 += __shfl_xor_sync(0xffffffffu, sum1, 1); sum1 += __shfl_xor_sync(0xffffffffu, sum1, 2);
        l0 = l0*al0 + sum0; l1 = l1*al1 + sum1;
        #pragma unroll
        for (int nt = 0; nt < 8; nt++){
            acc_o[nt][0] *= al0; acc_o[nt][1] *= al0;
            acc_o[nt][2] *= al1; acc_o[nt][3] *= al1;
        }
        #pragma unroll
        for (int k2 = 0; k2 < 4; k2++){
            uint32_t ph[4], pl4[4];
            split2(s[2*k2][0],   s[2*k2][1],   ph[0], pl4[0]);
            split2(s[2*k2][2],   s[2*k2][3],   ph[1], pl4[1]);
            split2(s[2*k2+1][0], s[2*k2+1][1], ph[2], pl4[2]);
            split2(s[2*k2+1][2], s[2*k2+1][3], ph[3], pl4[3]);
            #pragma unroll
            for (int ng = 0; ng < 4; ng++){
                uint32_t vh[4], vl[4];
                uint32_t va = kb0 + 2*(2*FPL + (k2*16 + (lane&7) + ((lane>>3)&1)*8)*FSTR + ng*16 + (lane>>4)*8);
                ldsm4t(vh, va); ldsm4t(vl, va + 2*FPL);
                mma16816(acc_o[2*ng],   ph,  vh[0], vh[1]);
                mma16816(acc_o[2*ng],   pl4, vh[0], vh[1]);
                mma16816(acc_o[2*ng],   ph,  vl[0], vl[1]);
                mma16816(acc_o[2*ng+1], ph,  vh[2], vh[3]);
                mma16816(acc_o[2*ng+1], pl4, vh[2], vh[3]);
                mma16816(acc_o[2*ng+1], ph,  vl[2], vl[3]);
            }
        }
        __syncthreads();
    }

    float inv0 = 1.f/l0, inv1 = 1.f/l1;
    long ro0 = ((long)((b*SS + s0 + rl0)*NHQ) + h)*HDH;
    long ro1 = ((long)((b*SS + s0 + rl1)*NHQ) + h)*HDH;
    #pragma unroll
    for (int nt = 0; nt < 8; nt++){
        int d = nt*8 + colb;
        uint32_t hi, lo;
        split2(acc_o[nt][0]*inv0, acc_o[nt][1]*inv0, hi, lo);
        *(uint32_t*)&Oh[ro0 + d] = hi; *(uint32_t*)&Ol[ro0 + d] = lo;
        split2(acc_o[nt][2]*inv1, acc_o[nt][3]*inv1, hi, lo);
        *(uint32_t*)&Oh[ro1 + d] = hi; *(uint32_t*)&Ol[ro1 + d] = lo;
    }
}

// ---- router ----
__global__ __launch_bounds__(128) void router_kernel(
    const float* __restrict__ hn, const float* __restrict__ rw,
    float* __restrict__ probs, int* __restrict__ ridx, float* __restrict__ rwt){
    int t = blockIdx.x;
    __shared__ float sl[EE];
    if (threadIdx.x < EE) sl[threadIdx.x] = 0.f;
    __syncthreads();
    const float* xr = hn + (long)t*DD;
    float part[EE] = {};
    for (int d = threadIdx.x; d < DD; d += 128){
        float xv = xr[d];
        #pragma unroll
        for (int e = 0; e < EE; e++) part[e] += xv*rw[d*EE+e];
    }
    #pragma unroll
    for (int e = 0; e < EE; e++)
        for (int off = 16; off; off >>= 1) part[e] += __shfl_xor_sync(0xffffffffu, part[e], off);
    if ((threadIdx.x&31) == 0)
        #pragma unroll
        for (int e = 0; e < EE; e++) atomicAdd(&sl[e], part[e]);
    __syncthreads();
    if (threadIdx.x == 0){
        float mx = sl[0];
        #pragma unroll
        for (int e = 1; e < EE; e++) mx = fmaxf(mx, sl[e]);
        float p[EE], se = 0.f;
        #pragma unroll
        for (int e = 0; e < EE; e++){ p[e] = __expf(sl[e]-mx); se += p[e]; }
        #pragma unroll
        for (int e = 0; e < EE; e++){ p[e] /= se; probs[t*EE+e] = p[e]; }
        int i0 = 0;
        #pragma unroll
        for (int e = 1; e < EE; e++) if (p[e] > p[i0]) i0 = e;
        int i1 = (i0 == 0) ? 1 : 0;
        #pragma unroll
        for (int e = 0; e < EE; e++) if (e != i0 && p[e] > p[i1]) i1 = e;
        float w0 = p[i0], w1 = p[i1], swv = w0+w1;
        ridx[2*t] = i0; ridx[2*t+1] = i1;
        rwt[2*t] = w0/swv; rwt[2*t+1] = w1/swv;
    }
}

// ---- routing build ----
__global__ __launch_bounds__(256) void route_build_kernel(
    const float* __restrict__ probs, const int* __restrict__ ridx,
    const float* __restrict__ rwt, float* aux_out, float* util_out,
    int* ecnt, int* eidx, float* ew){
    __shared__ float psum[EE]; __shared__ int counts[EE];
    if (threadIdx.x < EE) psum[threadIdx.x] = 0.f;
    __syncthreads();
    float part[EE] = {};
    for (int t = threadIdx.x; t < TT; t += 256)
        #pragma unroll
        for (int e = 0; e < EE; e++) part[e] += probs[t*EE+e];
    #pragma unroll
    for (int e = 0; e < EE; e++)
        for (int off = 16; off; off >>= 1) part[e] += __shfl_xor_sync(0xffffffffu, part[e], off);
    if ((threadIdx.x&31) == 0)
        #pragma unroll
        for (int e = 0; e < EE; e++) atomicAdd(&psum[e], part[e]);
    __syncthreads();
    {
        int e = threadIdx.x>>5, lane = threadIdx.x&31;
        int cnt = 0;
        for (int t0 = 0; t0 < TT; t0 += 32){
            int t = t0 + lane;
            int i0 = ridx[2*t], i1 = ridx[2*t+1];
            bool mem = (i0 == e) || (i1 == e);
            unsigned msk = __ballot_sync(0xffffffffu, mem);
            if (mem){
                int pos = cnt + __popc(msk & ((1u<<lane)-1));
                if (pos < CAPE){
                    eidx[e*CAPE+pos] = t;
                    ew[e*CAPE+pos] = (i0 == e) ? rwt[2*t] : rwt[2*t+1];
                }
            }
            cnt += __popc(msk);
        }
        if (lane == 0){ counts[e] = cnt; ecnt[e] = min(cnt, CAPE); }
    }
    __syncthreads();
    if (threadIdx.x == 0){
        float aux = 0.f, util = 0.f;
        #pragma unroll
        for (int e = 0; e < EE; e++){
            aux += (psum[e]/(float)TT)*((float)counts[e]/(float)TT);
            if (counts[e] > 0) util += 1.f;
        }
        *aux_out = (float)EE*aux; *util_out = util/(float)EE*100.f;
    }
}

// ---- host helpers ----
static CDesc cd(const float* in, bf16* hi, bf16* lo, int Rin, int Cin, int Rp, int Cp){
    CDesc c; c.in=in; c.hi=hi; c.lo=lo; c.Rin=Rin; c.Cin=Cin; c.Rp=Rp; c.Cp=Cp; return c;
}
static GDesc gd(const bf16* Ab, long Asz, const bf16* Bb, long Bsz, float* C, const float* res,
                const int* aidx, const int* cidx, const float* rs, const int* Mcnt,
                int M, int N, int K, int ldb, int ldc, bf16* Chi = nullptr, bf16* Clo = nullptr,
                const bf16* B2b = nullptr, long B2sz = 0){
    GDesc g; g.Ah=Ab; g.Al=Ab+Asz; g.Bh=Bb; g.Bl=Bb+Bsz;
    g.B2h = B2b; g.B2l = B2b ? B2b+B2sz : nullptr;
    g.C=C; g.res=res; g.aidx=aidx; g.cidx=cidx; g.rs=rs; g.Mcnt=Mcnt; g.Chi=Chi; g.Clo=Clo;
    g.M=M; g.N=N; g.K=K; g.ldb=ldb; g.ldc=ldc;
    return g;
}

extern "C" void kernel_launch(void* const* d_in, const int* in_sizes, int n_in,
                              void* d_out, int out_size){
    const float* x      = (const float*)d_in[0];
    const float* cosp   = (const float*)d_in[1];
    const float* sinp   = (const float*)d_in[2];
    const float* attn_w = (const float*)d_in[4];
    const float* moe_w  = (const float*)d_in[5];
    const float* wq = (const float*)d_in[6];
    const float* wk = (const float*)d_in[7];
    const float* wv = (const float*)d_in[8];
    const float* wo = (const float*)d_in[9];
    const float* rw = (const float*)d_in[10];
    const float* ew1 = (const float*)d_in[11];
    const float* ew2 = (const float*)d_in[12];
    const float* ew3 = (const float*)d_in[13];
    const float* sw1 = (const float*)d_in[14];
    const float* sw2 = (const float*)d_in[15];
    const float* sw3 = (const float*)d_in[16];

    float* out  = (float*)d_out;
    float* aux  = out + (long)TT*DD;
    float* util = aux + 1;
    float* nk   = util + 1;
    float* nv   = nk + (long)TT*NKVH*HDH;

    float *p_q,*p_k,*p_h,*p_hn,*p_probs,*p_rwt,*p_ew;
    int *p_ridx,*p_ecnt,*p_eidx;
    bf16 *b_xn,*b_ao,*b_hn,*b_h1s,*b_eh1,*b_qb,*b_kb,*b_vb,*b_wq,*b_wk,*b_wv,*b_wo,*b_sw1,*b_sw3,*b_sw2,*b_ew1,*b_ew3,*b_ew2;
    cudaGetSymbolAddress((void**)&p_q,g_q);     cudaGetSymbolAddress((void**)&p_k,g_k);
    cudaGetSymbolAddress((void**)&p_h,g_h);     cudaGetSymbolAddress((void**)&p_hn,g_hn);
    cudaGetSymbolAddress((void**)&p_probs,g_probs); cudaGetSymbolAddress((void**)&p_ridx,g_ridx);
    cudaGetSymbolAddress((void**)&p_rwt,g_rwt); cudaGetSymbolAddress((void**)&p_ecnt,g_ecnt);
    cudaGetSymbolAddress((void**)&p_eidx,g_eidx); cudaGetSymbolAddress((void**)&p_ew,g_ew);
    cudaGetSymbolAddress((void**)&b_xn,g_xnb);  cudaGetSymbolAddress((void**)&b_ao,g_aob);
    cudaGetSymbolAddress((void**)&b_hn,g_hnb);  cudaGetSymbolAddress((void**)&b_h1s,g_h1sb);
    cudaGetSymbolAddress((void**)&b_eh1,g_eh1b);
    cudaGetSymbolAddress((void**)&b_qb,g_qb);   cudaGetSymbolAddress((void**)&b_kb,g_kb);
    cudaGetSymbolAddress((void**)&b_vb,g_vb);
    cudaGetSymbolAddress((void**)&b_wq,g_wqb);  cudaGetSymbolAddress((void**)&b_wk,g_wkb);
    cudaGetSymbolAddress((void**)&b_wv,g_wvb);  cudaGetSymbolAddress((void**)&b_wo,g_wob);
    cudaGetSymbolAddress((void**)&b_sw1,g_sw1b);cudaGetSymbolAddress((void**)&b_sw3,g_sw3b);
    cudaGetSymbolAddress((void**)&b_sw2,g_sw2b);
    cudaGetSymbolAddress((void**)&b_ew1,g_ew1b);cudaGetSymbolAddress((void**)&b_ew3,g_ew3b);
    cudaGetSymbolAddress((void**)&b_ew2,g_ew2b);

    const int GS0 = 2*(2*ASZH + 2*BSZH)*2;
    const int GS1 = 2*(2*ASZH + 4*BSZH)*2;
    cudaFuncSetAttribute(bgemm_kernel<0>, cudaFuncAttributeMaxDynamicSharedMemorySize, GS0);
    cudaFuncSetAttribute(bgemm_kernel<1>, cudaFuncAttributeMaxDynamicSharedMemorySize, GS1);
    cudaFuncSetAttribute(flash_tc_kernel, cudaFuncAttributeMaxDynamicSharedMemorySize, FSMEM);

    const long SZ_XN = (long)TT*DD, SZ_WQ = (long)DD*DD, SZ_WKV = (long)DD*256;
    const long SZ_SW13 = (long)DD*HIDP, SZ_SW2 = (long)HIDP*DD;
    const long SZ_EW13 = (long)EE*DD*HIDP, SZ_EW2 = (long)EE*HIDP*DD;
    const long SZ_H1S = (long)TT*HIDP, SZ_EH1 = (long)EE*CAPE*HIDP;
    const long QPL = (long)TT*NHQ*HDH, KPL = (long)TT*NKVH*HDH;

    rmsnorm_kernel<<<TT,256>>>(x, attn_w, nullptr, b_xn, b_xn+SZ_XN);

    {
        CBatch cb; int n = 0;
        cb.d[n++] = cd(wq, b_wq, b_wq+SZ_WQ, DD, DD, DD, DD);
        cb.d[n++] = cd(wk, b_wk, b_wk+SZ_WKV, DD, 256, DD, 256);
        cb.d[n++] = cd(wv, b_wv, b_wv+SZ_WKV, DD, 256, DD, 256);
        cb.d[n++] = cd(wo, b_wo, b_wo+SZ_WQ, DD, DD, DD, DD);
        cb.d[n++] = cd(sw1, b_sw1, b_sw1+SZ_SW13, DD, HIDM, DD, HIDP);
        cb.d[n++] = cd(sw3, b_sw3, b_sw3+SZ_SW13, DD, HIDM, DD, HIDP);
        cb.d[n++] = cd(sw2, b_sw2, b_sw2+SZ_SW2, HIDM, DD, HIDP, DD);
        for (int e = 0; e < EE; e++)
            cb.d[n++] = cd(ew1+(long)e*DD*HIDM, b_ew1+(long)e*DD*HIDP, b_ew1+SZ_EW13+(long)e*DD*HIDP, DD, HIDM, DD, HIDP);
        convert_kernel<<<dim3(160,1,n),256>>>(cb);
    }
    {
        CBatch cb; int n = 0;
        for (int e = 0; e < EE; e++)
            cb.d[n++] = cd(ew3+(long)e*DD*HIDM, b_ew3+(long)e*DD*HIDP, b_ew3+SZ_EW13+(long)e*DD*HIDP, DD, HIDM, DD, HIDP);
        for (int e = 0; e < EE; e++)
            cb.d[n++] = cd(ew2+(long)e*HIDM*DD, b_ew2+(long)e*HIDP*DD, b_ew2+SZ_EW2+(long)e*HIDP*DD, HIDM, DD, HIDP, DD);
        convert_kernel<<<dim3(160,1,n),256>>>(cb);
    }

    {
        GBatch gb;
        gb.d[0] = gd(b_xn,SZ_XN, b_wq,SZ_WQ, p_q, 0,0,0,0,0, TT,1024,1024,1024,1024);
        gb.d[1] = gd(b_xn,SZ_XN, b_wk,SZ_WKV, p_k, 0,0,0,0,0, TT,256,1024,256,256);
        gb.d[2] = gd(b_xn,SZ_XN, b_wv,SZ_WKV, nv, 0,0,0,0,0, TT,256,1024,256,256, b_vb, b_vb+KPL);
        bgemm_kernel<0><<<dim3(16,32,3),256,GS0>>>(gb);
    }

    rope2_kernel<<<2560,256>>>(p_q, p_k, nk, b_qb, b_qb+QPL, b_kb, b_kb+KPL, cosp, sinp);

    flash_tc_kernel<<<dim3(SS/64,NHQ/2,BB),256,FSMEM>>>(b_qb, b_kb, b_vb, b_ao, b_ao+SZ_XN);

    { GBatch gb;
      gb.d[0] = gd(b_ao,SZ_XN, b_wo,SZ_WQ, p_h, x,0,0,0,0, TT,1024,1024,1024,1024);
      bgemm_kernel<0><<<dim3(16,32,1),256,GS0>>>(gb); }

    rmsnorm_kernel<<<TT,256>>>(p_h, moe_w, p_hn, b_hn, b_hn+SZ_XN);

    router_kernel<<<TT,128>>>(p_hn, rw, p_probs, p_ridx, p_rwt);
    route_build_kernel<<<1,256>>>(p_probs, p_ridx, p_rwt, aux, util, p_ecnt, p_eidx, p_ew);

    {
        GBatch gb;
        gb.d[0] = gd(b_hn,SZ_XN, b_sw1,SZ_SW13, 0,0,0,0,0,0, TT,HIDP,1024,HIDP,HIDP,
                     b_h1s, b_h1s+SZ_H1S, b_sw3, SZ_SW13);
        for (int e = 0; e < EE; e++)
            gb.d[1+e] = gd(b_hn,SZ_XN, b_ew1+(long)e*DD*HIDP, SZ_EW13,
                           0,0, p_eidx+e*CAPE, 0,0, p_ecnt+e,
                           CAPE,HIDP,1024,HIDP,HIDP,
                           b_eh1+(long)e*CAPE*HIDP, b_eh1+SZ_EH1+(long)e*CAPE*HIDP,
                           b_ew3+(long)e*DD*HIDP, SZ_EW13);
        bgemm_kernel<1><<<dim3(22,32,9),256,GS1>>>(gb);
    }

    { GBatch gb;
      gb.d[0] = gd(b_h1s,SZ_H1S, b_sw2,SZ_SW2, out, p_h,0,0,0,0, TT,1024,HIDP,1024,1024);
      bgemm_kernel<0><<<dim3(16,32,1),256,GS0>>>(gb); }

    {
        GBatch gb;
        for (int e = 0; e < EE; e++)
            gb.d[e] = gd(b_eh1+(long)e*CAPE*HIDP, SZ_EH1, b_ew2+(long)e*HIDP*DD, SZ_EW2,
                         out, 0, 0, p_eidx+e*CAPE, p_ew+e*CAPE, p_ecnt+e,
                         CAPE,1024,HIDP,1024,1024);
        bgemm_kernel<0><<<dim3(16,10,8),256,GS0>>>(gb);
    }
}

// round 17
// speedup vs baseline: 1.0174x; 1.0174x over previous
#include <cuda_runtime.h>
#include <cuda_bf16.h>
#include <cstdint>

#define BB 2
#define SS 2048
#define DD 1024
#define NHQ 16
#define NKVH 4
#define HDH 64
#define EE 8
#define HIDM 1365
#define HIDP 1376
#define CAPE 1280
#define TT 4096

typedef __nv_bfloat16 bf16;

__device__ __align__(128) float g_q  [TT*DD];
__device__ __align__(128) float g_k  [TT*NKVH*HDH];
__device__ __align__(128) float g_h  [TT*DD];
__device__ __align__(128) float g_hn [TT*DD];
__device__ float g_probs[TT*EE];
__device__ int   g_ridx[TT*2];
__device__ float g_rwt [TT*2];
__device__ int   g_ecnt[EE];
__device__ int   g_eidx[EE*CAPE];
__device__ float g_ew  [EE*CAPE];
__device__ int   g_iota[TT];
__device__ float g_ones[TT];

__device__ __align__(128) bf16 g_xnb [2*TT*DD];
__device__ __align__(128) bf16 g_aob [2*TT*DD];
__device__ __align__(128) bf16 g_hnb [2*TT*DD];
__device__ __align__(128) bf16 g_h1sb[2*TT*HIDP];
__device__ __align__(128) bf16 g_eh1b[2*EE*CAPE*HIDP];
__device__ __align__(128) bf16 g_qb  [2*TT*DD];
__device__ __align__(128) bf16 g_kb  [2*TT*256];
__device__ __align__(128) bf16 g_vb  [2*TT*256];
__device__ __align__(128) bf16 g_wqb [2*DD*DD];
__device__ __align__(128) bf16 g_wkb [2*DD*256];
__device__ __align__(128) bf16 g_wvb [2*DD*256];
__device__ __align__(128) bf16 g_wob [2*DD*DD];
__device__ __align__(128) bf16 g_sw1b[2*DD*HIDP];
__device__ __align__(128) bf16 g_sw3b[2*DD*HIDP];
__device__ __align__(128) bf16 g_sw2b[2*HIDP*DD];
__device__ __align__(128) bf16 g_ew1b[2*EE*DD*HIDP];
__device__ __align__(128) bf16 g_ew3b[2*EE*DD*HIDP];
__device__ __align__(128) bf16 g_ew2b[2*EE*HIDP*DD];

__device__ __forceinline__ void cpa16(uint32_t s, const void* g){
    asm volatile("cp.async.cg.shared.global [%0], [%1], 16;"::"r"(s),"l"(g));
}
__device__ __forceinline__ void cp_commit(){ asm volatile("cp.async.commit_group;"); }
template<int N> __device__ __forceinline__ void cp_wait(){ asm volatile("cp.async.wait_group %0;"::"n"(N)); }
__device__ __forceinline__ void ldsm4(uint32_t (&r)[4], uint32_t a){
    asm volatile("ldmatrix.sync.aligned.m8n8.x4.shared.b16 {%0,%1,%2,%3}, [%4];"
        :"=r"(r[0]),"=r"(r[1]),"=r"(r[2]),"=r"(r[3]):"r"(a));
}
__device__ __forceinline__ void ldsm4t(uint32_t (&r)[4], uint32_t a){
    asm volatile("ldmatrix.sync.aligned.m8n8.x4.trans.shared.b16 {%0,%1,%2,%3}, [%4];"
        :"=r"(r[0]),"=r"(r[1]),"=r"(r[2]),"=r"(r[3]):"r"(a));
}
__device__ __forceinline__ void mma16816(float (&d)[4], const uint32_t (&a)[4], uint32_t b0, uint32_t b1){
    asm volatile("mma.sync.aligned.m16n8k16.row.col.f32.bf16.bf16.f32 "
        "{%0,%1,%2,%3}, {%4,%5,%6,%7}, {%8,%9}, {%0,%1,%2,%3};"
        :"+f"(d[0]),"+f"(d[1]),"+f"(d[2]),"+f"(d[3])
        :"r"(a[0]),"r"(a[1]),"r"(a[2]),"r"(a[3]),"r"(b0),"r"(b1));
}
__device__ __forceinline__ void split2(float x, float y, uint32_t& hi, uint32_t& lo){
    __nv_bfloat162 h = __floats2bfloat162_rn(x, y);
    __nv_bfloat162 l = __floats2bfloat162_rn(x - __bfloat162float(h.x), y - __bfloat162float(h.y));
    hi = *(uint32_t*)&h; lo = *(uint32_t*)&l;
}

// ---- split convert fp32 -> hi/lo bf16 (4-wide vectorized) ----
struct CDesc { const float* in; bf16* hi; bf16* lo; int Rin, Cin, Rp, Cp; };
struct CBatch { CDesc d[16]; };
__global__ __launch_bounds__(256) void convert_kernel(CBatch cb){
    CDesc c = cb.d[blockIdx.z];
    long tot4 = ((long)c.Rp * c.Cp) >> 2;
    for (long q = (long)blockIdx.x*blockDim.x + threadIdx.x; q < tot4; q += (long)gridDim.x*blockDim.x){
        long i = q << 2;
        int r = (int)(i / c.Cp), cc = (int)(i % c.Cp);
        uint32_t hv[2], lv[2];
        const float* src = c.in + (long)r*c.Cin + cc;
        bool rin = r < c.Rin;
        #pragma unroll
        for (int p = 0; p < 2; p++){
            float v0 = (rin && cc+2*p   < c.Cin) ? src[2*p]   : 0.f;
            float v1 = (rin && cc+2*p+1 < c.Cin) ? src[2*p+1] : 0.f;
            split2(v0, v1, hv[p], lv[p]);
        }
        *(uint2*)&c.hi[i] = make_uint2(hv[0], hv[1]);
        *(uint2*)&c.lo[i] = make_uint2(lv[0], lv[1]);
    }
}

// ---- batched split-bf16 HMMA GEMM, 128x64 CTA tile (DUAL: fused w1||w3 + silu) ----
struct GDesc {
    const bf16 *Ah, *Al, *Bh, *Bl, *B2h, *B2l;
    float* C; const float* res;
    const int* aidx; const int* cidx; const float* rs; const int* Mcnt;
    bf16 *Chi, *Clo;
    int M, N, K, ldb, ldc;
};
struct GBatch { GDesc d[18]; };

#define ASTR 40
#define BSTR 72
#define ASZH (128*ASTR)
#define BSZH (32*BSTR)

template<int DUAL>
__global__ __launch_bounds__(256, DUAL ? 2 : 3) void bgemm_kernel(GBatch gb){
    GDesc g = gb.d[blockIdx.z];
    const int Meff = g.Mcnt ? *g.Mcnt : g.M;
    const int row0 = blockIdx.y*128, col0 = blockIdx.x*64;
    if (row0 >= Meff || col0 >= g.N) return;
    const int BUFH_ = 2*ASZH + (DUAL?4:2)*BSZH;

    extern __shared__ bf16 sh[];
    const int tid = threadIdx.x;
    const int ra = tid>>2, ca = (tid&3)*8;
    const int rbn = tid>>3, cbn = (tid&7)*8;
    int ar0, ar1;
    { int r0g = row0+ra, r1g = row0+ra+64;
      if (g.aidx){ ar0 = g.aidx[min(r0g,Meff-1)]; ar1 = g.aidx[min(r1g,Meff-1)]; }
      else { ar0 = r0g < g.M ? r0g : g.M-1; ar1 = r1g < g.M ? r1g : g.M-1; } }
    const char* pAh0 = (const char*)(g.Ah + (long)ar0*g.K + ca);
    const char* pAl0 = (const char*)(g.Al + (long)ar0*g.K + ca);
    const char* pAh1 = (const char*)(g.Ah + (long)ar1*g.K + ca);
    const char* pAl1 = (const char*)(g.Al + (long)ar1*g.K + ca);
    const bool bval = (col0+cbn) < g.ldb;
    const long boff = (long)rbn*g.ldb + col0+cbn;
    const long bstride = 64L*g.ldb;

    const uint32_t smb = (uint32_t)__cvta_generic_to_shared(sh);
    const uint32_t aH0 = 2*(ra*ASTR+ca), aH1 = aH0 + 2*64*ASTR;
    const uint32_t aL0 = aH0 + 2*ASZH, aL1 = aH1 + 2*ASZH;
    const uint32_t bO = 2*(2*ASZH + rbn*BSTR + cbn);

    if (!bval){
        uint4 z = make_uint4(0,0,0,0);
        #pragma unroll
        for (int buf = 0; buf < 2; buf++)
            for (int p = 0; p < (DUAL?4:2); p++)
                *(uint4*)(sh + buf*BUFH_ + 2*ASZH + p*BSZH + rbn*BSTR + cbn) = z;
    }
    const int NT = g.K >> 5;
    auto issue = [&](int t, int buf){
        uint32_t o = smb + (uint32_t)buf*(BUFH_*2);
        long ta = (long)t*64;
        cpa16(o+aH0, pAh0+ta); cpa16(o+aH1, pAh1+ta);
        cpa16(o+aL0, pAl0+ta); cpa16(o+aL1, pAl1+ta);
        if (bval){
            long tb = (long)t*bstride;
            cpa16(o+bO,          (const char*)(g.Bh+boff)+tb);
            cpa16(o+bO+2*BSZH,   (const char*)(g.Bl+boff)+tb);
            if (DUAL){
                cpa16(o+bO+4*BSZH, (const char*)(g.B2h+boff)+tb);
                cpa16(o+bO+6*BSZH, (const char*)(g.B2l+boff)+tb);
            }
        }
    };
    issue(0,0); cp_commit();

    const int warp = tid>>5, lane = tid&31;
    const int wm = (warp&3)*32, wn = (warp>>2)*32;
    float acc[2][4][4] = {};
    float acc2[DUAL?2:1][4][4] = {};
    const uint32_t aLd = (uint32_t)((wm + (lane&15))*ASTR + (lane>>4)*8);
    const uint32_t bLd = (uint32_t)(((lane&7) + ((lane>>3)&1)*8)*BSTR + wn + (lane>>4)*8);

    for (int t = 0; t < NT; t++){
        if (t+1 < NT){ issue(t+1, (t+1)&1); cp_commit(); cp_wait<1>(); }
        else cp_wait<0>();
        __syncthreads();
        const uint32_t base = smb + (uint32_t)(t&1)*(BUFH_*2);
        #pragma unroll
        for (int ks = 0; ks < 2; ks++){
            uint32_t bh[2][4], bl[2][4], b2h[2][4], b2l[2][4];
            #pragma unroll
            for (int np = 0; np < 2; np++){
                uint32_t ad = base + 2*(2*ASZH + bLd + ks*16*BSTR + np*16);
                ldsm4t(bh[np], ad); ldsm4t(bl[np], ad + 2*BSZH);
                if (DUAL){ ldsm4t(b2h[np], ad + 4*BSZH); ldsm4t(b2l[np], ad + 6*BSZH); }
            }
            #pragma unroll
            for (int mt = 0; mt < 2; mt++){
                uint32_t aa = base + 2*(aLd + mt*16*ASTR + ks*16);
                uint32_t ah[4], al[4];
                ldsm4(ah, aa); ldsm4(al, aa + 2*ASZH);
                #pragma unroll
                for (int nt = 0; nt < 4; nt++){
                    int np = nt>>1, o = (nt&1)*2;
                    mma16816(acc[mt][nt], ah, bh[np][o], bh[np][o+1]);
                    mma16816(acc[mt][nt], al, bh[np][o], bh[np][o+1]);
                    mma16816(acc[mt][nt], ah, bl[np][o], bl[np][o+1]);
                    if (DUAL){
                        mma16816(acc2[mt][nt], ah, b2h[np][o], b2h[np][o+1]);
                        mma16816(acc2[mt][nt], al, b2h[np][o], b2h[np][o+1]);
                        mma16816(acc2[mt][nt], ah, b2l[np][o], b2l[np][o+1]);
                    }
                }
            }
        }
        __syncthreads();
    }

    const int Nt = g.N, ldc = g.ldc;
    #pragma unroll
    for (int mt = 0; mt < 2; mt++)
    #pragma unroll
    for (int dh = 0; dh < 2; dh++){
        int r = row0 + wm + mt*16 + (lane>>2) + dh*8;
        if (r >= Meff) continue;
        #pragma unroll
        for (int nt = 0; nt < 4; nt++){
            int c = col0 + wn + nt*8 + (lane&3)*2;
            float v0 = acc[mt][nt][dh*2], v1 = acc[mt][nt][dh*2+1];
            if (DUAL){
                if (c+1 < Nt){
                    float w0 = acc2[mt][nt][dh*2], w1 = acc2[mt][nt][dh*2+1];
                    float s0 = (v0/(1.f+__expf(-v0)))*w0;
                    float s1 = (v1/(1.f+__expf(-v1)))*w1;
                    long ro = (long)r*ldc + c;
                    uint32_t hi, lo; split2(s0, s1, hi, lo);
                    *(uint32_t*)&g.Chi[ro] = hi;
                    *(uint32_t*)&g.Clo[ro] = lo;
                }
            } else if (g.cidx){
                float w = g.rs[r]; long ro = (long)g.cidx[r]*ldc;
                if (c < Nt)   atomicAdd(&g.C[ro+c], w*v0);
                if (c+1 < Nt) atomicAdd(&g.C[ro+c+1], w*v1);
            } else {
                long ro = (long)r*ldc;
                if (g.res){ if (c < Nt) v0 += g.res[ro+c]; if (c+1 < Nt) v1 += g.res[ro+c+1]; }
                if (g.C){
                    if (c < Nt)   g.C[ro+c]   = v0;
                    if (c+1 < Nt) g.C[ro+c+1] = v1;
                }
                if (g.Chi && c+1 < Nt){
                    uint32_t hi, lo; split2(v0, v1, hi, lo);
                    *(uint32_t*)&g.Chi[ro+c] = hi;
                    *(uint32_t*)&g.Clo[ro+c] = lo;
                }
            }
        }
    }
}

// ---- rmsnorm (optionally copies src into cpy and fills iota/ones) ----
__global__ __launch_bounds__(256) void rmsnorm_kernel(
    const float* __restrict__ x, const float* __restrict__ w,
    float* __restrict__ yf, bf16* __restrict__ yh, bf16* __restrict__ yl,
    float* __restrict__ cpy, int* __restrict__ iota, float* __restrict__ ones){
    long t = blockIdx.x;
    const float* xr = x + t*DD;
    float ss = 0.f;
    for (int d = threadIdx.x; d < DD; d += 256){ float v = xr[d]; ss += v*v; }
    for (int off = 16; off; off >>= 1) ss += __shfl_xor_sync(0xffffffffu, ss, off);
    __shared__ float red[8]; __shared__ float rfac;
    if ((threadIdx.x&31) == 0) red[threadIdx.x>>5] = ss;
    __syncthreads();
    if (threadIdx.x == 0){
        float s2 = 0.f;
        #pragma unroll
        for (int i = 0; i < 8; i++) s2 += red[i];
        rfac = rsqrtf(s2/(float)DD + 1e-6f);
        if (iota){ iota[t] = (int)t; ones[t] = 1.f; }
    }
    __syncthreads();
    float r = rfac;
    for (int d = threadIdx.x; d < DD; d += 256){
        float xv = xr[d];
        float v = xv*r*w[d];
        if (yf) yf[t*DD + d] = v;
        if (cpy) cpy[t*DD + d] = xv;
        bf16 h = __float2bfloat16(v);
        yh[t*DD + d] = h;
        yl[t*DD + d] = __float2bfloat16(v - __bfloat162float(h));
    }
}

// ---- combined RoPE ----
__global__ void rope2_kernel(const float* __restrict__ qin, const float* __restrict__ kin,
    float* __restrict__ nk, bf16* __restrict__ qh, bf16* __restrict__ ql,
    bf16* __restrict__ kh, bf16* __restrict__ kl,
    const float* __restrict__ cs, const float* __restrict__ sn){
    const int qtot = TT*NHQ*32, ktot = TT*NKVH*32;
    for (int idx = blockIdx.x*blockDim.x + threadIdx.x; idx < qtot + ktot; idx += gridDim.x*blockDim.x){
        const float* in; bf16 *oh, *ol; float* of; int H, i;
        if (idx < qtot){ in = qin; oh = qh; ol = ql; of = nullptr; H = NHQ; i = idx; }
        else { in = kin; oh = kh; ol = kl; of = nk; H = NKVH; i = idx - qtot; }
        int d = i & 31, h = (i>>5)%H, t = i/(32*H), s = t & (SS-1);
        long base = ((long)t*H + h)*HDH + d;
        float x1 = in[base], x2 = in[base+32];
        float c = cs[s*HDH+d], si = sn[s*HDH+d];
        float y1 = x1*c - x2*si, y2 = x1*si + x2*c;
        if (of){ of[base] = y1; of[base+32] = y2; }
        bf16 h1 = __float2bfloat16(y1), h2 = __float2bfloat16(y2);
        oh[base] = h1; oh[base+32] = h2;
        ol[base]    = __float2bfloat16(y1 - __bfloat162float(h1));
        ol[base+32] = __float2bfloat16(y2 - __bfloat162float(h2));
    }
}

// ---- flash attention: 2 heads/CTA share K/V, double-buffered ----
#define FSTR 72
#define FPL (64*FSTR)
#define FSMEM (12*FPL*2)

__global__ __launch_bounds__(256) void flash_tc_kernel(
    const bf16* __restrict__ Qb, const bf16* __restrict__ Kb,
    const bf16* __restrict__ Vb, bf16* __restrict__ Oh, bf16* __restrict__ Ol){
    const int b = blockIdx.z, hp2 = blockIdx.y, qt = blockIdx.x;
    const int hk = hp2 >> 1, s0 = qt*64;
    extern __shared__ bf16 fs[];
    const uint32_t smb = (uint32_t)__cvta_generic_to_shared(fs);
    const int tid = threadIdx.x, wid = tid>>5, lane = tid&31;
    const int wg = wid>>2, w4 = wid&3;
    const int h = hp2*2 + wg;
    const long QPL = (long)TT*NHQ*HDH, KPL = (long)TT*NKVH*HDH;
    const int wrow = w4*16;

    for (int i = tid; i < 2048; i += 256){
        int pl = i>>9, r = (i>>3)&63, c8 = (i&7)*8;
        const bf16* src = Qb + (long)(pl&1)*QPL + ((long)((b*SS+s0+r)*NHQ) + hp2*2 + (pl>>1))*HDH + c8;
        cpa16(smb + 2*(pl*FPL + r*FSTR + c8), src);
    }
    auto loadKV = [&](int kt, int buf){
        for (int i = tid; i < 2048; i += 256){
            int pl = i>>9, r = (i>>3)&63, c8 = (i&7)*8;
            const bf16* basep = (pl < 2) ? Kb : Vb;
            const bf16* src = basep + (long)(pl&1)*KPL + ((long)((b*SS+kt*64+r)*NKVH) + hk)*HDH + c8;
            cpa16(smb + 2*((4 + buf*4 + pl)*FPL + r*FSTR + c8), src);
        }
        cp_commit();
    };
    loadKV(0, 0);

    float acc_o[8][4] = {};
    float m0 = -1e30f, m1 = -1e30f, l0 = 0.f, l1 = 0.f;
    const int colb = (lane&3)*2;
    const int rl0 = wrow + (lane>>2), rl1 = rl0 + 8;
    const uint32_t aQh = smb + 2*((2*wg)*FPL + (wrow + (lane&15))*FSTR + (lane>>4)*8);
    const uint32_t aQl = aQh + 2*FPL;

    for (int kt = 0; kt <= qt; kt++){
        if (kt+1 <= qt){ loadKV(kt+1, (kt+1)&1); cp_wait<1>(); }
        else cp_wait<0>();
        __syncthreads();
        const uint32_t kb0 = smb + 2*(uint32_t)((4 + (kt&1)*4)*FPL);

        float s[8][4] = {};
        #pragma unroll
        for (int kst = 0; kst < 4; kst++){
            uint32_t ah[4], al[4];
            ldsm4(ah, aQh + 2*(kst*16));
            ldsm4(al, aQl + 2*(kst*16));
            #pragma unroll
            for (int ng = 0; ng < 4; ng++){
                uint32_t kh[4], kl[4];
                uint32_t ka = kb0 + 2*((ng*16 + (lane&15))*FSTR + kst*16 + (lane>>4)*8);
                ldsm4(kh, ka); ldsm4(kl, ka + 2*FPL);
                mma16816(s[2*ng],   ah, kh[0], kh[2]);
                mma16816(s[2*ng],   al, kh[0], kh[2]);
                mma16816(s[2*ng],   ah, kl[0], kl[2]);
                mma16816(s[2*ng+1], ah, kh[1], kh[3]);
                mma16816(s[2*ng+1], al, kh[1], kh[3]);
                mma16816(s[2*ng+1], ah, kl[1], kl[3]);
            }
        }
        const bool diag = (kt == qt);
        #pragma unroll
        for (int nt = 0; nt < 8; nt++){
            int c = nt*8 + colb;
            #pragma unroll
            for (int j = 0; j < 4; j++) s[nt][j] *= 0.125f;
            if (diag){
                if (c   > rl0) s[nt][0] = -1e30f;
                if (c+1 > rl0) s[nt][1] = -1e30f;
                if (c   > rl1) s[nt][2] = -1e30f;
                if (c+1 > rl1) s[nt][3] = -1e30f;
            }
        }
        float rm0 = -1e30f, rm1 = -1e30f;
        #pragma unroll
        for (int nt = 0; nt < 8; nt++){
            rm0 = fmaxf(rm0, fmaxf(s[nt][0], s[nt][1]));
            rm1 = fmaxf(rm1, fmaxf(s[nt][2], s[nt][3]));
        }
        rm0 = fmaxf(rm0, __shfl_xor_sync(0xffffffffu, rm0, 1));
        rm0 = fmaxf(rm0, __shfl_xor_sync(0xffffffffu, rm0, 2));
        rm1 = fmaxf(rm1, __shfl_xor_sync(0xffffffffu, rm1, 1));
        rm1 = fmaxf(rm1, __shfl_xor_sync(0xffffffffu, rm1, 2));
        float mn0 = fmaxf(m0, rm0), mn1 = fmaxf(m1, rm1);
        float al0 = __expf(m0 - mn0), al1 = __expf(m1 - mn1);
        m0 = mn0; m1 = mn1;
        float sum0 = 0.f, sum1 = 0.f;
        #pragma unroll
        for (int nt = 0; nt < 8; nt++){
            s[nt][0] = __expf(s[nt][0] - mn0); s[nt][1] = __expf(s[nt][1] - mn0);
            s[nt][2] = __expf(s[nt][2] - mn1); s[nt][3] = __expf(s[nt][3] - mn1);
            sum0 += s[nt][0] + s[nt][1]; sum1 += s[nt][2] + s[nt][3];
        }
        sum0 += __shfl_xor_sync(0xffffffffu, sum0, 1); sum0 += __shfl_xor_sync(0xffffffffu, sum0, 2);
        sum1 += __shfl_xor_sync(0xffffffffu, sum1, 1); sum1 += __shfl_xor_sync(0xffffffffu, sum1, 2);
        l0 = l0*al0 + sum0; l1 = l1*al1 + sum1;
        #pragma unroll
        for (int nt = 0; nt < 8; nt++){
            acc_o[nt][0] *= al0; acc_o[nt][1] *= al0;
            acc_o[nt][2] *= al1; acc_o[nt][3] *= al1;
        }
        #pragma unroll
        for (int k2 = 0; k2 < 4; k2++){
            uint32_t ph[4], pl4[4];
            split2(s[2*k2][0],   s[2*k2][1],   ph[0], pl4[0]);
            split2(s[2*k2][2],   s[2*k2][3],   ph[1], pl4[1]);
            split2(s[2*k2+1][0], s[2*k2+1][1], ph[2], pl4[2]);
            split2(s[2*k2+1][2], s[2*k2+1][3], ph[3], pl4[3]);
            #pragma unroll
            for (int ng = 0; ng < 4; ng++){
                uint32_t vh[4], vl[4];
                uint32_t va = kb0 + 2*(2*FPL + (k2*16 + (lane&7) + ((lane>>3)&1)*8)*FSTR + ng*16 + (lane>>4)*8);
                ldsm4t(vh, va); ldsm4t(vl, va + 2*FPL);
                mma16816(acc_o[2*ng],   ph,  vh[0], vh[1]);
                mma16816(acc_o[2*ng],   pl4, vh[0], vh[1]);
                mma16816(acc_o[2*ng],   ph,  vl[0], vl[1]);
                mma16816(acc_o[2*ng+1], ph,  vh[2], vh[3]);
                mma16816(acc_o[2*ng+1], pl4, vh[2], vh[3]);
                mma16816(acc_o[2*ng+1], ph,  vl[2], vl[3]);
            }
        }
        __syncthreads();
    }

    float inv0 = 1.f/l0, inv1 = 1.f/l1;
    long ro0 = ((long)((b*SS + s0 + rl0)*NHQ) + h)*HDH;
    long ro1 = ((long)((b*SS + s0 + rl1)*NHQ) + h)*HDH;
    #pragma unroll
    for (int nt = 0; nt < 8; nt++){
        int d = nt*8 + colb;
        uint32_t hi, lo;
        split2(acc_o[nt][0]*inv0, acc_o[nt][1]*inv0, hi, lo);
        *(uint32_t*)&Oh[ro0 + d] = hi; *(uint32_t*)&Ol[ro0 + d] = lo;
        split2(acc_o[nt][2]*inv1, acc_o[nt][3]*inv1, hi, lo);
        *(uint32_t*)&Oh[ro1 + d] = hi; *(uint32_t*)&Ol[ro1 + d] = lo;
    }
}

// ---- router ----
__global__ __launch_bounds__(128) void router_kernel(
    const float* __restrict__ hn, const float* __restrict__ rw,
    float* __restrict__ probs, int* __restrict__ ridx, float* __restrict__ rwt){
    int t = blockIdx.x;
    __shared__ float sl[EE];
    if (threadIdx.x < EE) sl[threadIdx.x] = 0.f;
    __syncthreads();
    const float* xr = hn + (long)t*DD;
    float part[EE] = {};
    for (int d = threadIdx.x; d < DD; d += 128){
        float xv = xr[d];
        #pragma unroll
        for (int e = 0; e < EE; e++) part[e] += xv*rw[d*EE+e];
    }
    #pragma unroll
    for (int e = 0; e < EE; e++)
        for (int off = 16; off; off >>= 1) part[e] += __shfl_xor_sync(0xffffffffu, part[e], off);
    if ((threadIdx.x&31) == 0)
        #pragma unroll
        for (int e = 0; e < EE; e++) atomicAdd(&sl[e], part[e]);
    __syncthreads();
    if (threadIdx.x == 0){
        float mx = sl[0];
        #pragma unroll
        for (int e = 1; e < EE; e++) mx = fmaxf(mx, sl[e]);
        float p[EE], se = 0.f;
        #pragma unroll
        for (int e = 0; e < EE; e++){ p[e] = __expf(sl[e]-mx); se += p[e]; }
        #pragma unroll
        for (int e = 0; e < EE; e++){ p[e] /= se; probs[t*EE+e] = p[e]; }
        int i0 = 0;
        #pragma unroll
        for (int e = 1; e < EE; e++) if (p[e] > p[i0]) i0 = e;
        int i1 = (i0 == 0) ? 1 : 0;
        #pragma unroll
        for (int e = 0; e < EE; e++) if (e != i0 && p[e] > p[i1]) i1 = e;
        float w0 = p[i0], w1 = p[i1], swv = w0+w1;
        ridx[2*t] = i0; ridx[2*t+1] = i1;
        rwt[2*t] = w0/swv; rwt[2*t+1] = w1/swv;
    }
}

// ---- routing build ----
__global__ __launch_bounds__(256) void route_build_kernel(
    const float* __restrict__ probs, const int* __restrict__ ridx,
    const float* __restrict__ rwt, float* aux_out, float* util_out,
    int* ecnt, int* eidx, float* ew){
    __shared__ float psum[EE]; __shared__ int counts[EE];
    if (threadIdx.x < EE) psum[threadIdx.x] = 0.f;
    __syncthreads();
    float part[EE] = {};
    for (int t = threadIdx.x; t < TT; t += 256)
        #pragma unroll
        for (int e = 0; e < EE; e++) part[e] += probs[t*EE+e];
    #pragma unroll
    for (int e = 0; e < EE; e++)
        for (int off = 16; off; off >>= 1) part[e] += __shfl_xor_sync(0xffffffffu, part[e], off);
    if ((threadIdx.x&31) == 0)
        #pragma unroll
        for (int e = 0; e < EE; e++) atomicAdd(&psum[e], part[e]);
    __syncthreads();
    {
        int e = threadIdx.x>>5, lane = threadIdx.x&31;
        int cnt = 0;
        for (int t0 = 0; t0 < TT; t0 += 32){
            int t = t0 + lane;
            int i0 = ridx[2*t], i1 = ridx[2*t+1];
            bool mem = (i0 == e) || (i1 == e);
            unsigned msk = __ballot_sync(0xffffffffu, mem);
            if (mem){
                int pos = cnt + __popc(msk & ((1u<<lane)-1));
                if (pos < CAPE){
                    eidx[e*CAPE+pos] = t;
                    ew[e*CAPE+pos] = (i0 == e) ? rwt[2*t] : rwt[2*t+1];
                }
            }
            cnt += __popc(msk);
        }
        if (lane == 0){ counts[e] = cnt; ecnt[e] = min(cnt, CAPE); }
    }
    __syncthreads();
    if (threadIdx.x == 0){
        float aux = 0.f, util = 0.f;
        #pragma unroll
        for (int e = 0; e < EE; e++){
            aux += (psum[e]/(float)TT)*((float)counts[e]/(float)TT);
            if (counts[e] > 0) util += 1.f;
        }
        *aux_out = (float)EE*aux; *util_out = util/(float)EE*100.f;
    }
}

// ---- host helpers ----
static CDesc cd(const float* in, bf16* hi, bf16* lo, int Rin, int Cin, int Rp, int Cp){
    CDesc c; c.in=in; c.hi=hi; c.lo=lo; c.Rin=Rin; c.Cin=Cin; c.Rp=Rp; c.Cp=Cp; return c;
}
static GDesc gd(const bf16* Ab, long Asz, const bf16* Bb, long Bsz, float* C, const float* res,
                const int* aidx, const int* cidx, const float* rs, const int* Mcnt,
                int M, int N, int K, int ldb, int ldc, bf16* Chi = nullptr, bf16* Clo = nullptr,
                const bf16* B2b = nullptr, long B2sz = 0){
    GDesc g; g.Ah=Ab; g.Al=Ab+Asz; g.Bh=Bb; g.Bl=Bb+Bsz;
    g.B2h = B2b; g.B2l = B2b ? B2b+B2sz : nullptr;
    g.C=C; g.res=res; g.aidx=aidx; g.cidx=cidx; g.rs=rs; g.Mcnt=Mcnt; g.Chi=Chi; g.Clo=Clo;
    g.M=M; g.N=N; g.K=K; g.ldb=ldb; g.ldc=ldc;
    return g;
}

extern "C" void kernel_launch(void* const* d_in, const int* in_sizes, int n_in,
                              void* d_out, int out_size){
    const float* x      = (const float*)d_in[0];
    const float* cosp   = (const float*)d_in[1];
    const float* sinp   = (const float*)d_in[2];
    const float* attn_w = (const float*)d_in[4];
    const float* moe_w  = (const float*)d_in[5];
    const float* wq = (const float*)d_in[6];
    const float* wk = (const float*)d_in[7];
    const float* wv = (const float*)d_in[8];
    const float* wo = (const float*)d_in[9];
    const float* rw = (const float*)d_in[10];
    const float* ew1 = (const float*)d_in[11];
    const float* ew2 = (const float*)d_in[12];
    const float* ew3 = (const float*)d_in[13];
    const float* sw1 = (const float*)d_in[14];
    const float* sw2 = (const float*)d_in[15];
    const float* sw3 = (const float*)d_in[16];

    float* out  = (float*)d_out;
    float* aux  = out + (long)TT*DD;
    float* util = aux + 1;
    float* nk   = util + 1;
    float* nv   = nk + (long)TT*NKVH*HDH;

    float *p_q,*p_k,*p_h,*p_hn,*p_probs,*p_rwt,*p_ew,*p_ones;
    int *p_ridx,*p_ecnt,*p_eidx,*p_iota;
    bf16 *b_xn,*b_ao,*b_hn,*b_h1s,*b_eh1,*b_qb,*b_kb,*b_vb,*b_wq,*b_wk,*b_wv,*b_wo,*b_sw1,*b_sw3,*b_sw2,*b_ew1,*b_ew3,*b_ew2;
    cudaGetSymbolAddress((void**)&p_q,g_q);     cudaGetSymbolAddress((void**)&p_k,g_k);
    cudaGetSymbolAddress((void**)&p_h,g_h);     cudaGetSymbolAddress((void**)&p_hn,g_hn);
    cudaGetSymbolAddress((void**)&p_probs,g_probs); cudaGetSymbolAddress((void**)&p_ridx,g_ridx);
    cudaGetSymbolAddress((void**)&p_rwt,g_rwt); cudaGetSymbolAddress((void**)&p_ecnt,g_ecnt);
    cudaGetSymbolAddress((void**)&p_eidx,g_eidx); cudaGetSymbolAddress((void**)&p_ew,g_ew);
    cudaGetSymbolAddress((void**)&p_iota,g_iota); cudaGetSymbolAddress((void**)&p_ones,g_ones);
    cudaGetSymbolAddress((void**)&b_xn,g_xnb);  cudaGetSymbolAddress((void**)&b_ao,g_aob);
    cudaGetSymbolAddress((void**)&b_hn,g_hnb);  cudaGetSymbolAddress((void**)&b_h1s,g_h1sb);
    cudaGetSymbolAddress((void**)&b_eh1,g_eh1b);
    cudaGetSymbolAddress((void**)&b_qb,g_qb);   cudaGetSymbolAddress((void**)&b_kb,g_kb);
    cudaGetSymbolAddress((void**)&b_vb,g_vb);
    cudaGetSymbolAddress((void**)&b_wq,g_wqb);  cudaGetSymbolAddress((void**)&b_wk,g_wkb);
    cudaGetSymbolAddress((void**)&b_wv,g_wvb);  cudaGetSymbolAddress((void**)&b_wo,g_wob);
    cudaGetSymbolAddress((void**)&b_sw1,g_sw1b);cudaGetSymbolAddress((void**)&b_sw3,g_sw3b);
    cudaGetSymbolAddress((void**)&b_sw2,g_sw2b);
    cudaGetSymbolAddress((void**)&b_ew1,g_ew1b);cudaGetSymbolAddress((void**)&b_ew3,g_ew3b);
    cudaGetSymbolAddress((void**)&b_ew2,g_ew2b);

    const int GS0 = 2*(2*ASZH + 2*BSZH)*2;
    const int GS1 = 2*(2*ASZH + 4*BSZH)*2;
    cudaFuncSetAttribute(bgemm_kernel<0>, cudaFuncAttributeMaxDynamicSharedMemorySize, GS0);
    cudaFuncSetAttribute(bgemm_kernel<1>, cudaFuncAttributeMaxDynamicSharedMemorySize, GS1);
    cudaFuncSetAttribute(flash_tc_kernel, cudaFuncAttributeMaxDynamicSharedMemorySize, FSMEM);

    const long SZ_XN = (long)TT*DD, SZ_WQ = (long)DD*DD, SZ_WKV = (long)DD*256;
    const long SZ_SW13 = (long)DD*HIDP, SZ_SW2 = (long)HIDP*DD;
    const long SZ_EW13 = (long)EE*DD*HIDP, SZ_EW2 = (long)EE*HIDP*DD;
    const long SZ_H1S = (long)TT*HIDP, SZ_EH1 = (long)EE*CAPE*HIDP;
    const long QPL = (long)TT*NHQ*HDH, KPL = (long)TT*NKVH*HDH;

    rmsnorm_kernel<<<TT,256>>>(x, attn_w, nullptr, b_xn, b_xn+SZ_XN, nullptr, nullptr, nullptr);

    {
        CBatch cb; int n = 0;
        cb.d[n++] = cd(wq, b_wq, b_wq+SZ_WQ, DD, DD, DD, DD);
        cb.d[n++] = cd(wk, b_wk, b_wk+SZ_WKV, DD, 256, DD, 256);
        cb.d[n++] = cd(wv, b_wv, b_wv+SZ_WKV, DD, 256, DD, 256);
        cb.d[n++] = cd(wo, b_wo, b_wo+SZ_WQ, DD, DD, DD, DD);
        cb.d[n++] = cd(sw1, b_sw1, b_sw1+SZ_SW13, DD, HIDM, DD, HIDP);
        cb.d[n++] = cd(sw3, b_sw3, b_sw3+SZ_SW13, DD, HIDM, DD, HIDP);
        cb.d[n++] = cd(sw2, b_sw2, b_sw2+SZ_SW2, HIDM, DD, HIDP, DD);
        for (int e = 0; e < EE; e++)
            cb.d[n++] = cd(ew1+(long)e*DD*HIDM, b_ew1+(long)e*DD*HIDP, b_ew1+SZ_EW13+(long)e*DD*HIDP, DD, HIDM, DD, HIDP);
        convert_kernel<<<dim3(160,1,n),256>>>(cb);
    }
    {
        CBatch cb; int n = 0;
        for (int e = 0; e < EE; e++)
            cb.d[n++] = cd(ew3+(long)e*DD*HIDM, b_ew3+(long)e*DD*HIDP, b_ew3+SZ_EW13+(long)e*DD*HIDP, DD, HIDM, DD, HIDP);
        for (int e = 0; e < EE; e++)
            cb.d[n++] = cd(ew2+(long)e*HIDM*DD, b_ew2+(long)e*HIDP*DD, b_ew2+SZ_EW2+(long)e*HIDP*DD, HIDM, DD, HIDP, DD);
        convert_kernel<<<dim3(160,1,n),256>>>(cb);
    }

    {
        GBatch gb;
        gb.d[0] = gd(b_xn,SZ_XN, b_wq,SZ_WQ, p_q, 0,0,0,0,0, TT,1024,1024,1024,1024);
        gb.d[1] = gd(b_xn,SZ_XN, b_wk,SZ_WKV, p_k, 0,0,0,0,0, TT,256,1024,256,256);
        gb.d[2] = gd(b_xn,SZ_XN, b_wv,SZ_WKV, nv, 0,0,0,0,0, TT,256,1024,256,256, b_vb, b_vb+KPL);
        bgemm_kernel<0><<<dim3(16,32,3),256,GS0>>>(gb);
    }

    rope2_kernel<<<2560,256>>>(p_q, p_k, nk, b_qb, b_qb+QPL, b_kb, b_kb+KPL, cosp, sinp);

    flash_tc_kernel<<<dim3(SS/64,NHQ/2,BB),256,FSMEM>>>(b_qb, b_kb, b_vb, b_ao, b_ao+SZ_XN);

    { GBatch gb;
      gb.d[0] = gd(b_ao,SZ_XN, b_wo,SZ_WQ, p_h, x,0,0,0,0, TT,1024,1024,1024,1024);
      bgemm_kernel<0><<<dim3(16,32,1),256,GS0>>>(gb); }

    // moe rmsnorm: also copies h into out (base for atomic adds) and fills iota/ones
    rmsnorm_kernel<<<TT,256>>>(p_h, moe_w, p_hn, b_hn, b_hn+SZ_XN, out, p_iota, p_ones);

    router_kernel<<<TT,128>>>(p_hn, rw, p_probs, p_ridx, p_rwt);
    route_build_kernel<<<1,256>>>(p_probs, p_ridx, p_rwt, aux, util, p_ecnt, p_eidx, p_ew);

    {
        GBatch gb;
        gb.d[0] = gd(b_hn,SZ_XN, b_sw1,SZ_SW13, 0,0,0,0,0,0, TT,HIDP,1024,HIDP,HIDP,
                     b_h1s, b_h1s+SZ_H1S, b_sw3, SZ_SW13);
        for (int e = 0; e < EE; e++)
            gb.d[1+e] = gd(b_hn,SZ_XN, b_ew1+(long)e*DD*HIDP, SZ_EW13,
                           0,0, p_eidx+e*CAPE, 0,0, p_ecnt+e,
                           CAPE,HIDP,1024,HIDP,HIDP,
                           b_eh1+(long)e*CAPE*HIDP, b_eh1+SZ_EH1+(long)e*CAPE*HIDP,
                           b_ew3+(long)e*DD*HIDP, SZ_EW13);
        bgemm_kernel<1><<<dim3(22,32,9),256,GS1>>>(gb);
    }

    // merged w2: shared (identity scatter, weight 1.0) + 8 experts, all atomicAdd into out
    {
        GBatch gb;
        gb.d[0] = gd(b_h1s,SZ_H1S, b_sw2,SZ_SW2, out, 0, 0, p_iota, p_ones, 0,
                     TT,1024,HIDP,1024,1024);
        for (int e = 0; e < EE; e++)
            gb.d[1+e] = gd(b_eh1+(long)e*CAPE*HIDP, SZ_EH1, b_ew2+(long)e*HIDP*DD, SZ_EW2,
                           out, 0, 0, p_eidx+e*CAPE, p_ew+e*CAPE, p_ecnt+e,
                           CAPE,1024,HIDP,1024,1024);
        bgemm_kernel<0><<<dim3(16,32,9),256,GS0>>>(gb);
    }
}